// round 12
// baseline (speedup 1.0000x reference)
#include <cuda_runtime.h>
#include <cuda_bf16.h>

#define BATCH 8
#define FDIM 16
#define NPTS 2048
#define TILE 128
#define NTILE (NPTS / TILE)             // 16
#define NOFF  (NTILE * (NTILE - 1) / 2) // 120
#define NTRI  (NOFF + NTILE)            // 136

// Dynamic smem layout (bytes)
#define SM_AS    0                       // 16x128 f32 = 8KB
#define SM_BS    8192                    // 8KB
#define SM_CNI   16384                   // 128 f32
#define SM_PI    16896
#define SM_CNJ   17408
#define SM_PJ    17920
#define SM_T     18432                   // 128x128 f32 = 64KB
#define SMEM_BYTES (18432 + 65536)       // 83968 -> 2 CTAs/SM

__device__ __forceinline__ float ex2f(float x)
{ float y; asm("ex2.approx.ftz.f32 %0, %1;" : "=f"(y) : "f"(x)); return y; }
__device__ __forceinline__ float lg2f(float x)
{ float y; asm("lg2.approx.ftz.f32 %0, %1;" : "=f"(y) : "f"(x)); return y; }

// Streaming (evict-first) 16B store.
__device__ __forceinline__ void stcs4(float4* p, float4 v)
{
    asm volatile("st.global.cs.v4.f32 [%0], {%1, %2, %3, %4};"
                 :: "l"(p), "f"(v.x), "f"(v.y), "f"(v.z), "f"(v.w) : "memory");
}

// Named barrier over 128 threads (warp-aligned group).
__device__ __forceinline__ void half_bar(int id)
{
    asm volatile("bar.sync %0, 128;" :: "r"(id) : "memory");
}

// 16B-unit index into the 128x128-float staging buffer T.
// Write phase: rl = tx*8+jj -> (rl>>2)&31 distinct across lanes -> conflict-free.
// Read phase: rows r and r+64 have swizzle masks differing in bit 4 -> their
// 16-unit column sets are disjoint -> conflict-free warp loads.
__device__ __forceinline__ int tsw(int rl, int c4)
{
    return rl * 32 + (c4 ^ ((rl >> 2) & 31));
}

// ---------------------------------------------------------------------------
// One 128x128 (i,j) tile per block, triangular tiles only (it <= jt).
// 256 threads, 8x8 micro-tile. Single prologue barrier: norms/momenta are
// computed from GMEM (L1-hot lines) overlapping the tile STS, instead of a
// second sync-separated smem pass. Mirror path: independent 128-thread halves.
// ---------------------------------------------------------------------------
__global__ __launch_bounds__(256, 2)
void qcd_main_kernel(const float* __restrict__ emb,
                     const float* __restrict__ alpha_p,
                     const float* __restrict__ beta_p,
                     float* __restrict__ out)
{
    extern __shared__ __align__(16) unsigned char smraw[];
    float (*As)[TILE] = reinterpret_cast<float(*)[TILE]>(smraw + SM_AS);
    float (*Bs)[TILE] = reinterpret_cast<float(*)[TILE]>(smraw + SM_BS);
    float* cni_s = reinterpret_cast<float*>(smraw + SM_CNI);
    float* pi_s  = reinterpret_cast<float*>(smraw + SM_PI);
    float* cnj_s = reinterpret_cast<float*>(smraw + SM_CNJ);
    float* pj_s  = reinterpret_cast<float*>(smraw + SM_PJ);
    float4* Tq   = reinterpret_cast<float4*>(smraw + SM_T);

    // Tile index: off-diagonal pairs first (it<jt), diagonal tiles in the tail.
    const int t = blockIdx.x;
    int it, jt;
    if (t < NOFF) {
        jt = (int)((1.0f + sqrtf(8.0f * (float)t + 1.0f)) * 0.5f);
        if (jt * (jt - 1) / 2 > t)        jt--;
        else if ((jt + 1) * jt / 2 <= t)  jt++;
        it = t - jt * (jt - 1) / 2;
    } else {
        it = jt = t - NOFF;
    }

    const int b  = blockIdx.y;
    const int i0 = it * TILE;
    const int j0 = jt * TILE;
    const int tid = threadIdx.x;

    const float* eb = emb + (size_t)b * FDIM * NPTS;

    // Tile loads: 2x (16 rows x 32 float4) over 256 threads.
#pragma unroll
    for (int k = 0; k < 2; ++k) {
        int q  = tid + k * 256;
        int f  = q >> 5;
        int n4 = q & 31;
        *(float4*)&As[f][n4 * 4] = *(const float4*)&eb[f * NPTS + i0 + n4 * 4];
        *(float4*)&Bs[f][n4 * 4] = *(const float4*)&eb[f * NPTS + j0 + n4 * 4];
    }

    // Norms & momenta straight from GMEM (lines are L1-hot from the loads
    // above) — overlaps the STS latency; no intermediate barrier needed.
    const float alpha2 = 2.0f * alpha_p[0];
    const float beta   = beta_p[0];
    const float cl     = -(beta * beta) * 1.4426950408889634f;
    const float m2cl   = -2.0f * cl;
    {
        const int n0   = (tid < 128) ? i0 : j0;
        const int lane = tid & 127;
        const float* col = eb + n0 + lane;
        float s = 0.0f, m = 1.0f;
#pragma unroll
        for (int f = 0; f < FDIM; ++f) {
            float v = __ldg(col + f * NPTS);
            s = fmaf(v, v, s);
            if (f == 4) m = v;
        }
        if (tid < 128) {
            cni_s[lane] = cl * s;
            pi_s [lane] = ex2f(alpha2 * lg2f(m));
        } else {
            cnj_s[lane] = cl * s;
            pj_s [lane] = ex2f(alpha2 * lg2f(m));
        }
    }
    __syncthreads();   // single prologue barrier

    const int tx = tid & 15;   // j sub-tile: cols tx*8 .. +7
    const int ty = tid >> 4;   // i sub-tile: rows ty*8 .. +7

    float acc[8][8];
#pragma unroll
    for (int ii = 0; ii < 8; ++ii)
#pragma unroll
        for (int jj = 0; jj < 8; ++jj) acc[ii][jj] = 0.0f;

    // Scalar mainloop: 4 LDS.128 + 64 FFMA per f-step.
#pragma unroll
    for (int f = 0; f < FDIM; ++f) {
        float4 a0 = *(const float4*)&As[f][ty * 8];
        float4 a1 = *(const float4*)&As[f][ty * 8 + 4];
        float4 b0 = *(const float4*)&Bs[f][tx * 8];
        float4 b1 = *(const float4*)&Bs[f][tx * 8 + 4];
        float av[8] = {a0.x, a0.y, a0.z, a0.w, a1.x, a1.y, a1.z, a1.w};
        float bv[8] = {b0.x, b0.y, b0.z, b0.w, b1.x, b1.y, b1.z, b1.w};
#pragma unroll
        for (int ii = 0; ii < 8; ++ii)
#pragma unroll
            for (int jj = 0; jj < 8; ++jj)
                acc[ii][jj] = fmaf(av[ii], bv[jj], acc[ii][jj]);
    }

    float cni[8], pi[8], cnj[8], pj[8];
#pragma unroll
    for (int k = 0; k < 8; ++k) {
        cni[k] = cni_s[ty * 8 + k];
        pi[k]  = pi_s [ty * 8 + k];
        cnj[k] = cnj_s[tx * 8 + k];
        pj[k]  = pj_s [tx * 8 + k];
    }

    float* orow = out + (size_t)b * NPTS * NPTS + (size_t)(i0 + ty * 8) * NPTS + j0 + tx * 8;
    const bool mirror = (it != jt);

    if (mirror) {
        // Compute all w in place (needed column-wise for staging).
#pragma unroll
        for (int ii = 0; ii < 8; ++ii)
#pragma unroll
            for (int jj = 0; jj < 8; ++jj) {
                float x = fmaf(m2cl, acc[ii][jj], cni[ii] + cnj[jj]);
                acc[ii][jj] = ex2f(fminf(pi[ii], pj[jj]) * x);
            }

        const int half = ty >> 3;          // 0: T units 0-15, 1: units 16-31

        // 1) Stage transposed tile into this half's T columns (on-chip, fast).
#pragma unroll
        for (int jj = 0; jj < 8; ++jj) {
            int rl = tx * 8 + jj;          // T row = local j
            Tq[tsw(rl, 2 * ty + 0)] =
                make_float4(acc[0][jj], acc[1][jj], acc[2][jj], acc[3][jj]);
            Tq[tsw(rl, 2 * ty + 1)] =
                make_float4(acc[4][jj], acc[5][jj], acc[6][jj], acc[7][jj]);
        }

        // 2) Direct STG stream — drains while we wait at the half barrier.
#pragma unroll
        for (int ii = 0; ii < 8; ++ii) {
            float4* dst = (float4*)(orow + (size_t)ii * NPTS);
            stcs4(dst,     make_float4(acc[ii][0], acc[ii][1], acc[ii][2], acc[ii][3]));
            stcs4(dst + 1, make_float4(acc[ii][4], acc[ii][5], acc[ii][6], acc[ii][7]));
        }

        // 3) Sync only within this half (warps 0-3 vs 4-7 independent).
        half_bar(1 + half);

        // 4) Mirror readback of this half's 64-column slab:
        //    each warp covers rows {r, r+64} (disjoint swizzled unit sets),
        //    lanes 0-15 -> row r, lanes 16-31 -> row r+64.
        {
            const int lane   = tid & 31;
            const int warpid = (tid & 127) >> 5;       // 0..3 within half
            const int c4     = half * 16 + (lane & 15);
            const int rsel   = (lane >> 4) * 64;       // 0 or 64
#pragma unroll
            for (int k = 0; k < 16; ++k) {
                int rl = warpid + k * 4 + rsel;        // rows 0..63 (+64)
                float* mrow = out + (size_t)b * NPTS * NPTS
                                  + (size_t)(j0 + rl) * NPTS + i0;
                stcs4((float4*)(mrow + c4 * 4), Tq[tsw(rl, c4)]);
            }
        }
    } else {
        // Diagonal tile: row-by-row compute + immediate store.
#pragma unroll
        for (int ii = 0; ii < 8; ++ii) {
            float w[8];
#pragma unroll
            for (int jj = 0; jj < 8; ++jj) {
                float x = fmaf(m2cl, acc[ii][jj], cni[ii] + cnj[jj]);
                w[jj]   = ex2f(fminf(pi[ii], pj[jj]) * x);
            }
            float4* dst = (float4*)(orow + (size_t)ii * NPTS);
            stcs4(dst,     make_float4(w[0], w[1], w[2], w[3]));
            stcs4(dst + 1, make_float4(w[4], w[5], w[6], w[7]));
        }
    }
}

// ---------------------------------------------------------------------------
extern "C" void kernel_launch(void* const* d_in, const int* in_sizes, int n_in,
                              void* d_out, int out_size)
{
    const float* emb     = (const float*)d_in[0];
    const float* alpha_p = (const float*)d_in[1];
    const float* beta_p  = (const float*)d_in[2];
    float* out = (float*)d_out;

    cudaFuncSetAttribute(qcd_main_kernel,
                         cudaFuncAttributeMaxDynamicSharedMemorySize, SMEM_BYTES);

    dim3 grid(NTRI, BATCH);   // 136 x 8 = 1088 CTAs
    qcd_main_kernel<<<grid, 256, SMEM_BYTES>>>(emb, alpha_p, beta_p, out);
}

// round 13
// speedup vs baseline: 1.0164x; 1.0164x over previous
#include <cuda_runtime.h>
#include <cuda_bf16.h>

#define BATCH 8
#define FDIM 16
#define NPTS 2048
#define TILE 128
#define NTILE (NPTS / TILE)             // 16
#define NOFF  (NTILE * (NTILE - 1) / 2) // 120 off-diagonal tile pairs
#define NTRI  (NOFF + NTILE)            // 136
#define NCTAS (NTRI * BATCH)            // 1088

// Dynamic smem layout (bytes)
#define SM_AS    0                       // 16x128 f32 = 8KB
#define SM_BS    8192                    // 8KB
#define SM_CNI   16384                   // 128 f32
#define SM_PI    16896
#define SM_CNJ   17408
#define SM_PJ    17920
#define SM_T     18432                   // 128x128 f32 = 64KB
#define SMEM_BYTES (18432 + 65536)       // 83968 -> 2 CTAs/SM

__device__ __forceinline__ float ex2f(float x)
{ float y; asm("ex2.approx.ftz.f32 %0, %1;" : "=f"(y) : "f"(x)); return y; }
__device__ __forceinline__ float lg2f(float x)
{ float y; asm("lg2.approx.ftz.f32 %0, %1;" : "=f"(y) : "f"(x)); return y; }

// Streaming (evict-first) 16B store.
__device__ __forceinline__ void stcs4(float4* p, float4 v)
{
    asm volatile("st.global.cs.v4.f32 [%0], {%1, %2, %3, %4};"
                 :: "l"(p), "f"(v.x), "f"(v.y), "f"(v.z), "f"(v.w) : "memory");
}

// Named barrier over 128 threads (warp-aligned group).
__device__ __forceinline__ void half_bar(int id)
{
    asm volatile("bar.sync %0, 128;" :: "r"(id) : "memory");
}

// 16B-unit index into the 128x128-float staging buffer T.
// Write phase: rl = tx*8+jj -> (rl>>2)&31 distinct across lanes -> conflict-free.
// Read phase: rows r and r+64 have swizzle masks differing in bit 4 -> their
// 16-unit column sets are disjoint -> conflict-free warp loads.
__device__ __forceinline__ int tsw(int rl, int c4)
{
    return rl * 32 + (c4 ^ ((rl >> 2) & 31));
}

// ---------------------------------------------------------------------------
// One 128x128 (i,j) tile per block, triangular tiles only (it <= jt).
// 256 threads, 8x8 micro-tile. R11 structure; 1D grid with all off-diagonal
// CTAs first and light diagonal CTAs last (tail-wave balancing).
// ---------------------------------------------------------------------------
__global__ __launch_bounds__(256, 2)
void qcd_main_kernel(const float* __restrict__ emb,
                     const float* __restrict__ alpha_p,
                     const float* __restrict__ beta_p,
                     float* __restrict__ out)
{
    extern __shared__ __align__(16) unsigned char smraw[];
    float (*As)[TILE] = reinterpret_cast<float(*)[TILE]>(smraw + SM_AS);
    float (*Bs)[TILE] = reinterpret_cast<float(*)[TILE]>(smraw + SM_BS);
    float* cni_s = reinterpret_cast<float*>(smraw + SM_CNI);
    float* pi_s  = reinterpret_cast<float*>(smraw + SM_PI);
    float* cnj_s = reinterpret_cast<float*>(smraw + SM_CNJ);
    float* pj_s  = reinterpret_cast<float*>(smraw + SM_PJ);
    float4* Tq   = reinterpret_cast<float4*>(smraw + SM_T);

    // 1D tile index: 960 off-diagonal CTAs first, 128 diagonal CTAs last.
    const int bid = blockIdx.x;
    int it, jt, b;
    if (bid < NOFF * BATCH) {
        const int t = bid >> 3;          // 0..119 (pair index)
        b = bid & 7;
        jt = (int)((1.0f + sqrtf(8.0f * (float)t + 1.0f)) * 0.5f);
        if (jt * (jt - 1) / 2 > t)        jt--;
        else if ((jt + 1) * jt / 2 <= t)  jt++;
        it = t - jt * (jt - 1) / 2;
    } else {
        const int d = bid - NOFF * BATCH;
        it = jt = d >> 3;
        b  = d & 7;
    }

    const int i0 = it * TILE;
    const int j0 = jt * TILE;
    const int tid = threadIdx.x;

    const float* eb = emb + (size_t)b * FDIM * NPTS;

    // Tile loads: 2x (16 rows x 32 float4) over 256 threads.
#pragma unroll
    for (int k = 0; k < 2; ++k) {
        int q  = tid + k * 256;
        int f  = q >> 5;
        int n4 = q & 31;
        *(float4*)&As[f][n4 * 4] = *(const float4*)&eb[f * NPTS + i0 + n4 * 4];
        *(float4*)&Bs[f][n4 * 4] = *(const float4*)&eb[f * NPTS + j0 + n4 * 4];
    }
    __syncthreads();

    // Norms (pre-scaled by c = -beta^2*log2e) and m^(2*alpha)
    const float alpha2 = 2.0f * alpha_p[0];
    const float beta   = beta_p[0];
    const float cl     = -(beta * beta) * 1.4426950408889634f;
    const float m2cl   = -2.0f * cl;
    if (tid < 128) {
        float s = 0.0f;
#pragma unroll
        for (int f = 0; f < FDIM; ++f) { float v = As[f][tid]; s = fmaf(v, v, s); }
        cni_s[tid] = cl * s;
        pi_s[tid]  = ex2f(alpha2 * lg2f(As[4][tid]));
    } else {
        int tt = tid - 128;
        float s = 0.0f;
#pragma unroll
        for (int f = 0; f < FDIM; ++f) { float v = Bs[f][tt]; s = fmaf(v, v, s); }
        cnj_s[tt] = cl * s;
        pj_s[tt]  = ex2f(alpha2 * lg2f(Bs[4][tt]));
    }
    __syncthreads();

    const int tx = tid & 15;   // j sub-tile: cols tx*8 .. +7
    const int ty = tid >> 4;   // i sub-tile: rows ty*8 .. +7

    float acc[8][8];
#pragma unroll
    for (int ii = 0; ii < 8; ++ii)
#pragma unroll
        for (int jj = 0; jj < 8; ++jj) acc[ii][jj] = 0.0f;

    // Scalar mainloop: 4 LDS.128 + 64 FFMA per f-step.
#pragma unroll
    for (int f = 0; f < FDIM; ++f) {
        float4 a0 = *(const float4*)&As[f][ty * 8];
        float4 a1 = *(const float4*)&As[f][ty * 8 + 4];
        float4 b0 = *(const float4*)&Bs[f][tx * 8];
        float4 b1 = *(const float4*)&Bs[f][tx * 8 + 4];
        float av[8] = {a0.x, a0.y, a0.z, a0.w, a1.x, a1.y, a1.z, a1.w};
        float bv[8] = {b0.x, b0.y, b0.z, b0.w, b1.x, b1.y, b1.z, b1.w};
#pragma unroll
        for (int ii = 0; ii < 8; ++ii)
#pragma unroll
            for (int jj = 0; jj < 8; ++jj)
                acc[ii][jj] = fmaf(av[ii], bv[jj], acc[ii][jj]);
    }

    float cni[8], pi[8], cnj[8], pj[8];
#pragma unroll
    for (int k = 0; k < 8; ++k) {
        cni[k] = cni_s[ty * 8 + k];
        pi[k]  = pi_s [ty * 8 + k];
        cnj[k] = cnj_s[tx * 8 + k];
        pj[k]  = pj_s [tx * 8 + k];
    }

    float* orow = out + (size_t)b * NPTS * NPTS + (size_t)(i0 + ty * 8) * NPTS + j0 + tx * 8;
    const bool mirror = (it != jt);

    if (mirror) {
        // Compute all w in place (needed column-wise for staging).
#pragma unroll
        for (int ii = 0; ii < 8; ++ii)
#pragma unroll
            for (int jj = 0; jj < 8; ++jj) {
                float x = fmaf(m2cl, acc[ii][jj], cni[ii] + cnj[jj]);
                acc[ii][jj] = ex2f(fminf(pi[ii], pj[jj]) * x);
            }

        const int half = ty >> 3;          // 0: T units 0-15, 1: units 16-31

        // 1) Stage transposed tile into this half's T columns (on-chip, fast).
#pragma unroll
        for (int jj = 0; jj < 8; ++jj) {
            int rl = tx * 8 + jj;          // T row = local j
            Tq[tsw(rl, 2 * ty + 0)] =
                make_float4(acc[0][jj], acc[1][jj], acc[2][jj], acc[3][jj]);
            Tq[tsw(rl, 2 * ty + 1)] =
                make_float4(acc[4][jj], acc[5][jj], acc[6][jj], acc[7][jj]);
        }

        // 2) Direct STG stream — drains while we wait at the half barrier.
#pragma unroll
        for (int ii = 0; ii < 8; ++ii) {
            float4* dst = (float4*)(orow + (size_t)ii * NPTS);
            stcs4(dst,     make_float4(acc[ii][0], acc[ii][1], acc[ii][2], acc[ii][3]));
            stcs4(dst + 1, make_float4(acc[ii][4], acc[ii][5], acc[ii][6], acc[ii][7]));
        }

        // 3) Sync only within this half (warps 0-3 vs 4-7 independent).
        half_bar(1 + half);

        // 4) Mirror readback of this half's 64-column slab:
        //    each warp covers rows {r, r+64} (disjoint swizzled unit sets),
        //    lanes 0-15 -> row r, lanes 16-31 -> row r+64.
        {
            const int lane   = tid & 31;
            const int warpid = (tid & 127) >> 5;       // 0..3 within half
            const int c4     = half * 16 + (lane & 15);
            const int rsel   = (lane >> 4) * 64;       // 0 or 64
#pragma unroll
            for (int k = 0; k < 16; ++k) {
                int rl = warpid + k * 4 + rsel;        // rows 0..63 (+64)
                float* mrow = out + (size_t)b * NPTS * NPTS
                                  + (size_t)(j0 + rl) * NPTS + i0;
                stcs4((float4*)(mrow + c4 * 4), Tq[tsw(rl, c4)]);
            }
        }
    } else {
        // Diagonal tile: row-by-row compute + immediate store.
#pragma unroll
        for (int ii = 0; ii < 8; ++ii) {
            float w[8];
#pragma unroll
            for (int jj = 0; jj < 8; ++jj) {
                float x = fmaf(m2cl, acc[ii][jj], cni[ii] + cnj[jj]);
                w[jj]   = ex2f(fminf(pi[ii], pj[jj]) * x);
            }
            float4* dst = (float4*)(orow + (size_t)ii * NPTS);
            stcs4(dst,     make_float4(w[0], w[1], w[2], w[3]));
            stcs4(dst + 1, make_float4(w[4], w[5], w[6], w[7]));
        }
    }
}

// ---------------------------------------------------------------------------
extern "C" void kernel_launch(void* const* d_in, const int* in_sizes, int n_in,
                              void* d_out, int out_size)
{
    const float* emb     = (const float*)d_in[0];
    const float* alpha_p = (const float*)d_in[1];
    const float* beta_p  = (const float*)d_in[2];
    float* out = (float*)d_out;

    cudaFuncSetAttribute(qcd_main_kernel,
                         cudaFuncAttributeMaxDynamicSharedMemorySize, SMEM_BYTES);

    qcd_main_kernel<<<NCTAS, 256, SMEM_BYTES>>>(emb, alpha_p, beta_p, out);
}